// round 15
// baseline (speedup 1.0000x reference)
#include <cuda_runtime.h>
#include <stdint.h>

#define OFF_LOGP 0
#define OFF_SD   6336
#define OFF_GD   6400
#define OFF_PRED 6464
#define OFF_GSOL 1286464

typedef unsigned long long u64;

__device__ float g_buf0[819200];
__device__ float g_buf1[819200];
__device__ float g_hWs[819200];
__device__ float g_hN[819200];
__device__ float g_A[640000];
__device__ float g_gum[633600];    // 99 * 6400
__device__ float g_gi0[2457600];   // [64][100][384] x@Wih0+bih0
__device__ float g_y[819200];      // [64][100][128] (x@Wq^T)*scale
__device__ float4 g_wpk0[12288];   // Wh0 full-width: [kk][col] (col 0..383)
__device__ float4 g_wpk12[24576];  // [m][kk][col], m=0:Wi1 m=1:Wh1

// ---------------- threefry2x32 (exact JAX) ----------------
__device__ __forceinline__ void tf2x32(uint32_t k0, uint32_t k1,
                                       uint32_t c0, uint32_t c1,
                                       uint32_t& o0, uint32_t& o1) {
  uint32_t ks0 = k0, ks1 = k1, ks2 = k0 ^ k1 ^ 0x1BD11BDAu;
  uint32_t x0 = c0 + ks0, x1 = c1 + ks1;
#define TF_RND(R) { x0 += x1; x1 = __funnelshift_l(x1, x1, (R)); x1 ^= x0; }
  TF_RND(13) TF_RND(15) TF_RND(26) TF_RND(6)   x0 += ks1; x1 += ks2 + 1u;
  TF_RND(17) TF_RND(29) TF_RND(16) TF_RND(24)  x0 += ks2; x1 += ks0 + 2u;
  TF_RND(13) TF_RND(15) TF_RND(26) TF_RND(6)   x0 += ks0; x1 += ks1 + 3u;
  TF_RND(17) TF_RND(29) TF_RND(16) TF_RND(24)  x0 += ks1; x1 += ks2 + 4u;
  TF_RND(13) TF_RND(15) TF_RND(26) TF_RND(6)   x0 += ks2; x1 += ks0 + 5u;
#undef TF_RND
  o0 = x0; o1 = x1;
}

// ---------------- f32x2 helpers ----------------
__device__ __forceinline__ u64 pk2(float lo, float hi) {
  u64 d; asm("mov.b64 %0, {%1, %2};" : "=l"(d) : "f"(lo), "f"(hi)); return d;
}
__device__ __forceinline__ void upk2(float& lo, float& hi, u64 d) {
  asm("mov.b64 {%0, %1}, %2;" : "=f"(lo), "=f"(hi) : "l"(d));
}
__device__ __forceinline__ void fma2(u64& acc, u64 a, u64 b) {
  asm("fma.rn.f32x2 %0, %1, %2, %3;" : "=l"(acc) : "l"(a), "l"(b), "l"(acc));
}
__device__ __forceinline__ float lsum(u64 d) {
  float lo, hi; upk2(lo, hi, d); return lo + hi;
}

// ---------------- mega front kernel: h0 | softA | pred | gzero ----------------
__global__ void k_front(const float* __restrict__ node, const float* __restrict__ demand,
                        const float* __restrict__ Wn0, const float* __restrict__ bn0,
                        const float* __restrict__ dis,
                        const float* __restrict__ We, const float* __restrict__ be,
                        const float* __restrict__ Wc, const float* __restrict__ bc,
                        float* __restrict__ out) {
  const int bx = blockIdx.x, tid = threadIdx.x;
  if (bx < 3200) {
    int idx = bx * 256 + tid;
    int row = idx >> 7, j = idx & 127;
    float v = bn0[j];
    v = fmaf(node[row * 2],     Wn0[j],       v);
    v = fmaf(node[row * 2 + 1], Wn0[128 + j], v);
    v = fmaf(demand[row],       Wn0[256 + j], v);
    g_buf0[idx] = fmaxf(v, 0.f);
  } else if (bx < 4000) {
    int row  = (bx - 3200) * 8 + (tid >> 5);
    int lane = tid & 31;
    const float* d = dis + row * 100;
    float v0 = -d[lane], v1 = -d[lane + 32], v2 = -d[lane + 64];
    float v3 = (lane + 96 < 100) ? -d[lane + 96] : -3.4e38f;
    float m = fmaxf(fmaxf(v0, v1), fmaxf(v2, v3));
#pragma unroll
    for (int o = 16; o > 0; o >>= 1) m = fmaxf(m, __shfl_xor_sync(0xffffffffu, m, o));
    float e0 = expf(v0 - m), e1 = expf(v1 - m), e2 = expf(v2 - m);
    float e3 = (lane + 96 < 100) ? expf(v3 - m) : 0.f;
    float s = e0 + e1 + e2 + e3;
#pragma unroll
    for (int o = 16; o > 0; o >>= 1) s += __shfl_xor_sync(0xffffffffu, s, o);
    float* Ar = g_A + row * 100;
    Ar[lane] = e0 / s; Ar[lane + 32] = e1 / s; Ar[lane + 64] = e2 / s;
    if (lane + 96 < 100) Ar[lane + 96] = e3 / s;
  } else if (bx < 4313) {
    __shared__ float wsm[4][128];
    for (int i = tid; i < 128; i += 256) {
      wsm[0][i] = We[i]; wsm[1][i] = be[i];
      wsm[2][i] = Wc[2 * i]; wsm[3][i] = Wc[2 * i + 1];
    }
    __syncthreads();
    int t0 = ((bx - 4000) * 256 + tid) * 8;
    if (t0 >= 640000) return;
    float d[8], y0[8], y1[8];
#pragma unroll
    for (int u = 0; u < 8; u++) {
      int pp = t0 + u;
      d[u] = (pp < 640000) ? __ldg(dis + pp) : 0.f;
      y0[u] = 0.f; y1[u] = 0.f;
    }
#pragma unroll 4
    for (int k = 0; k < 128; k++) {
      float we = wsm[0][k], bee = wsm[1][k];
      float w0 = wsm[2][k], w1 = wsm[3][k];
#pragma unroll
      for (int u = 0; u < 8; u++) {
        float e = fmaxf(fmaf(d[u], we, bee), 0.f);
        y0[u] = fmaf(e, w0, y0[u]);
        y1[u] = fmaf(e, w1, y1[u]);
      }
    }
    float bc0 = __ldg(bc), bc1 = __ldg(bc + 1);
#pragma unroll
    for (int u = 0; u < 8; u++) {
      int pp = t0 + u;
      if (pp < 640000) {
        float a = y0[u] + bc0, bb = y1[u] + bc1;
        float m = fmaxf(a, bb);
        float e0 = expf(a - m), e1 = expf(bb - m), s = e0 + e1;
        *(float2*)&out[OFF_PRED + pp * 2] = make_float2(e0 / s, e1 / s);
      }
    }
  } else {
    int idx = (bx - 4313) * 256 + tid;   // 625 blocks -> 160000 float4
    *(float4*)&out[OFF_GSOL + idx * 4] = make_float4(0.f, 0.f, 0.f, 0.f);
  }
}

// ---------------- hWs/hN; 16 rows per block, 256 threads ----------------
__global__ void k_gemm2(int src, const float* __restrict__ W1, const float* __restrict__ W2) {
  const float* h = src ? g_buf1 : g_buf0;
  __shared__ float acts[16][128];
  int tid = threadIdx.x;
  int j = tid & 127, half = tid >> 7;
  int row0 = blockIdx.x * 16;
  for (int i = tid; i < 2048; i += 256) acts[i >> 7][i & 127] = h[row0 * 128 + i];
  __syncthreads();
  float aS[8], aN[8];
#pragma unroll
  for (int r = 0; r < 8; r++) { aS[r] = 0.f; aN[r] = 0.f; }
#pragma unroll 8
  for (int k = 0; k < 128; k++) {
    float ws = __ldg(W1 + k * 128 + j);
    float wn = __ldg(W2 + k * 128 + j);
#pragma unroll
    for (int r = 0; r < 8; r++) {
      float a = acts[half * 8 + r][k];
      aS[r] = fmaf(a, ws, aS[r]);
      aN[r] = fmaf(a, wn, aN[r]);
    }
  }
#pragma unroll
  for (int r = 0; r < 8; r++) {
    g_hWs[(row0 + half * 8 + r) * 128 + j] = aS[r];
    g_hN [(row0 + half * 8 + r) * 128 + j] = aN[r];
  }
}

// ---------------- h_next = relu(hWs + A @ hN); grid (64,4), 512 threads ----------------
#define AGGR2_SMEM ((12800 + 2500) * 4)
__global__ void k_aggr(int dst) {
  extern __shared__ float sm[];
  float* hN_s = sm;
  float* A_s  = sm + 12800;
  int b = blockIdx.x, r0 = blockIdx.y * 25, tid = threadIdx.x;
  for (int i = tid; i < 12800; i += 512) hN_s[i] = g_hN[b * 12800 + i];
  for (int i = tid; i < 2500; i += 512)  A_s[i]  = g_A [b * 10000 + r0 * 100 + i];
  __syncthreads();
  float* ho = dst ? g_buf1 : g_buf0;
  int j = tid & 127, g = tid >> 7;
  for (int il = g; il < 25; il += 8) {
    int i2 = il + 4;
    bool two = i2 < 25;
    float a0 = 0.f, a1 = 0.f, c0 = 0.f, c1 = 0.f;
#pragma unroll 10
    for (int p = 0; p < 100; p += 2) {
      float h0v = hN_s[p * 128 + j], h1v = hN_s[(p + 1) * 128 + j];
      a0 = fmaf(A_s[il * 100 + p],     h0v, a0);
      a1 = fmaf(A_s[il * 100 + p + 1], h1v, a1);
      if (two) {
        c0 = fmaf(A_s[i2 * 100 + p],     h0v, c0);
        c1 = fmaf(A_s[i2 * 100 + p + 1], h1v, c1);
      }
    }
    int row = b * 100 + r0 + il;
    ho[row * 128 + j] = fmaxf(g_hWs[row * 128 + j] + a0 + a1, 0.f);
    if (two)
      ho[(row + 4) * 128 + j] = fmaxf(g_hWs[(row + 4) * 128 + j] + c0 + c1, 0.f);
  }
}

// ---------------- fused prep (gi0 | y | pack full-width | gumbel) ----------------
#define PREP_SMEM (17536 * 4)
__global__ void k_prep(const float* __restrict__ Wih, const float* __restrict__ bih,
                       const float* __restrict__ Wq,  const float* __restrict__ Whh) {
  extern __shared__ float smd[];
  const int bx = blockIdx.x, tid = threadIdx.x;
  if (bx < 800) {
    float* acts = smd;   // [8][128]
    int o = tid;
    int row0 = bx * 8;
    for (int i = o; i < 1024; i += 384) acts[i] = g_buf1[row0 * 128 + i];
    __syncthreads();
    float a[8];
    float bv = bih[o];
#pragma unroll
    for (int r = 0; r < 8; r++) a[r] = bv;
#pragma unroll 8
    for (int k = 0; k < 128; k++) {
      float w = __ldg(Wih + k * 384 + o);
#pragma unroll
      for (int r = 0; r < 8; r++) a[r] = fmaf(acts[r * 128 + k], w, a[r]);
    }
#pragma unroll
    for (int r = 0; r < 8; r++) g_gi0[(row0 + r) * 384 + o] = a[r];
  } else if (bx < 1600) {
    float* wq_t = smd;            // [j][k] padded 129
    float* acts = smd + 16512;    // [8][128]
    int row0 = (bx - 800) * 8;
    for (int i = tid; i < 16384; i += 384) {
      int k = i >> 7, j = i & 127;
      wq_t[j * 129 + k] = Wq[i];
    }
    for (int i = tid; i < 1024; i += 384) acts[i] = g_buf1[row0 * 128 + i];
    __syncthreads();
    if (tid < 128) {
      const float scale = (float)(1.0 / (double)sqrtf(128.0f));
      int k = tid;
      float a[8];
#pragma unroll
      for (int r = 0; r < 8; r++) a[r] = 0.f;
#pragma unroll 4
      for (int jj = 0; jj < 128; jj++) {
        float w = wq_t[jj * 129 + k];
#pragma unroll
        for (int r = 0; r < 8; r++) a[r] = fmaf(acts[r * 128 + jj], w, a[r]);
      }
#pragma unroll
      for (int r = 0; r < 8; r++) g_y[(row0 + r) * 128 + k] = a[r] * scale;
    }
  } else if (bx < 1984) {
    // full-width packs: [kk][col], col 0..383
    int idx = (bx - 1600) * 384 + tid;
    if (idx < 147456) {
      if (idx < 49152) {
        int f4 = idx >> 2, u = idx & 3;
        int col = f4 % 384, kk = f4 / 384;
        ((float*)g_wpk0)[idx] = Whh[(4 * kk + u) * 384 + col];
      } else {
        int i2 = idx - 49152;
        int m = i2 / 49152, r = i2 % 49152;
        int f4 = r >> 2, u = r & 3;
        int col = f4 % 384, kk = f4 / 384;
        const float* srcp = m ? (Whh + 49152) : (Wih + 49152);
        ((float*)g_wpk12)[i2] = srcp[(4 * kk + u) * 384 + col];
      }
    }
  } else {
    int t = bx - 1984;
    __shared__ uint32_t sk0, sk1;
    if (tid == 0) {
      uint32_t k0 = 0u, k1 = 42u, a, b;
      tf2x32(k0, k1, 0u, 0u, a, b); k0 = a; k1 = b;
      for (int i = 0; i < t; i++) { tf2x32(k0, k1, 0u, 0u, a, b); k0 = a; k1 = b; }
      tf2x32(k0, k1, 0u, 1u, a, b); sk0 = a; sk1 = b;
    }
    __syncthreads();
    const float TINY = 1.17549435e-38f;
    uint32_t s0 = sk0, s1 = sk1;
    for (int i = tid; i < 6400; i += 384) {
      uint32_t o0, o1;
      tf2x32(s0, s1, 0u, (uint32_t)i, o0, o1);
      uint32_t bits = o0 ^ o1;
      float f = __uint_as_float((bits >> 9) | 0x3f800000u) - 1.0f;
      float u = fmaxf(TINY, f + TINY);
      g_gum[t * 6400 + i] = -logf(-logf(u));
    }
  }
}

__device__ __forceinline__ float sigm(float x) { return 1.f / (1.f + expf(-x)); }

// ---------------- single-CTA decoder v7: no cluster, Wh0 resident, Y in regs ----
#define SOF_WH0   0        // float4[12288] = 49152 floats
#define SOF_GI2   49152    // float2[384]
#define SOF_GH2   49920    // float2[384]
#define SOF_GH1C  50688    // float2[384]
#define SOF_GIP   51456    // float2[768]
#define SOF_H0S   52992    // [2][128]
#define SOF_H0G   53248
#define SOF_H1S   53504
#define SOF_H1G   53760
#define SOF_GUM   54016    // [100]
#define SOF_LS    54116
#define SOF_LG    54216
#define SOF_SHI   54316    // int[2] (+pad)
#define SOF_RED   54320    // [4]
#define SOF_SOLS  54324    // int[100]
#define SOF_SOLG  54424    // int[100]
#define DEC7_FLOATS 54524
__global__ void __launch_bounds__(384, 1) k_decode(
    const float* __restrict__ dis, const float* __restrict__ bih,
    const float* __restrict__ bhh, float* __restrict__ out) {
  extern __shared__ float sm[];
  const int tid = threadIdx.x;
  const int b = blockIdx.x;
  const int lane = tid & 31, wrp = tid >> 5;

  float2* gi2  = (float2*)(sm + SOF_GI2);
  float2* gh2  = (float2*)(sm + SOF_GH2);
  float2* gh1c = (float2*)(sm + SOF_GH1C);
  float2* gip  = (float2*)(sm + SOF_GIP);
  float*  gums = sm + SOF_GUM;
  float*  ls   = sm + SOF_LS;
  float*  lg   = sm + SOF_LG;
  int*    shi  = (int*)(sm + SOF_SHI);
  float*  red  = sm + SOF_RED;
  int*    solS = (int*)(sm + SOF_SOLS);
  int*    solG = (int*)(sm + SOF_SOLG);

  const float4* wpk1F = g_wpk12;            // Wi1 full (streamed)
  const float4* wpk2F = g_wpk12 + 12288;    // Wh1 full (streamed)

  // prologue: stage Wh0 full, zero states, load persistent Y rows (tid<100)
  {
    float4* wh0s4 = (float4*)(sm + SOF_WH0);
    for (int i = tid; i < 12288; i += 384) wh0s4[i] = g_wpk0[i];
    for (int i = tid; i < 256; i += 384) {
      sm[SOF_H0S + i] = 0.f; sm[SOF_H0G + i] = 0.f;
      sm[SOF_H1S + i] = 0.f; sm[SOF_H1G + i] = 0.f;
    }
    if (tid == 0) { solS[0] = 0; solG[0] = 0; red[2] = 0.f; red[3] = 0.f; }
  }
  ulonglong2 Yr[16];   // persistent Y row (tid<100): 128 floats as 16 ul2 pairs? -> need 32
  ulonglong2 Yr2[16];
  if (tid < 100) {
    const float* yrow = g_y + b * 12800 + tid * 128;
#pragma unroll
    for (int kk = 0; kk < 16; kk++) Yr[kk]  = *(const ulonglong2*)&yrow[4 * kk];
#pragma unroll
    for (int kk = 0; kk < 16; kk++) Yr2[kk] = *(const ulonglong2*)&yrow[64 + 4 * kk];
  }
  float bh0_r = bhh[tid], bi1_r = bih[384 + tid], bh1_r = bhh[384 + tid];
  int cur_s = 0, cur_g = 0;
  __syncthreads();

  for (int t = 0; t < 99; t++) {
    const int p = t & 1;
    // ---- ph1: early loads ----
    if (tid < 100) gums[tid] = __ldg(&g_gum[t * 6400 + b * 100 + tid]);
    float gi_s = __ldg(&g_gi0[(b * 100 + cur_s) * 384 + tid]);
    float gi_g = __ldg(&g_gi0[(b * 100 + cur_g) * 384 + tid]);

    // ---- ph2: gh1 (streamed Wh1) + gh0 (resident Wh0), col = tid, f32x2 ----
    {
      u64 a0s = pk2(bh0_r, 0.f), a0g = a0s;
      u64 a1s = pk2(bh1_r, 0.f), a1g = a1s;
      const ulonglong2* h0s_ = (const ulonglong2*)(sm + SOF_H0S + p * 128);
      const ulonglong2* h0g_ = (const ulonglong2*)(sm + SOF_H0G + p * 128);
      const ulonglong2* h1s_ = (const ulonglong2*)(sm + SOF_H1S + p * 128);
      const ulonglong2* h1g_ = (const ulonglong2*)(sm + SOF_H1G + p * 128);
      const float* wh0s = sm + SOF_WH0;
#pragma unroll 16
      for (int kk = 0; kk < 32; kk++) {
        ulonglong2 w1 = *(const ulonglong2*)&wpk2F[kk * 384 + tid];
        ulonglong2 w0 = *(const ulonglong2*)&wh0s[(kk * 384 + tid) * 4];
        ulonglong2 hs0 = h0s_[kk], hg0 = h0g_[kk];
        ulonglong2 hs1 = h1s_[kk], hg1 = h1g_[kk];
        fma2(a0s, w0.x, hs0.x); fma2(a0g, w0.x, hg0.x);
        fma2(a0s, w0.y, hs0.y); fma2(a0g, w0.y, hg0.y);
        fma2(a1s, w1.x, hs1.x); fma2(a1g, w1.x, hg1.x);
        fma2(a1s, w1.y, hs1.y); fma2(a1g, w1.y, hg1.y);
      }
      gh2[tid]  = make_float2(lsum(a0s), lsum(a0g));
      gh1c[tid] = make_float2(lsum(a1s), lsum(a1g));
      gi2[tid]  = make_float2(gi_s, gi_g);
    }
    __syncthreads();

    // ---- gates#1 (tid<256: s=stream, j=hidden idx) ----
    if (tid < 256) {
      int s = tid >> 7, j = tid & 127;
      float ir, iz, in_, hr, hz, hn, hp;
      if (s == 0) {
        ir = gi2[j].x; iz = gi2[j + 128].x; in_ = gi2[j + 256].x;
        hr = gh2[j].x; hz = gh2[j + 128].x; hn  = gh2[j + 256].x;
        hp = sm[SOF_H0S + p * 128 + j];
      } else {
        ir = gi2[j].y; iz = gi2[j + 128].y; in_ = gi2[j + 256].y;
        hr = gh2[j].y; hz = gh2[j + 128].y; hn  = gh2[j + 256].y;
        hp = sm[SOF_H0G + p * 128 + j];
      }
      float r0 = sigm(ir + hr), z0 = sigm(iz + hz), n0 = tanhf(in_ + r0 * hn);
      float hv = (1.f - z0) * n0 + z0 * hp;
      sm[(s ? SOF_H0G : SOF_H0S) + (1 - p) * 128 + j] = hv;
    }
    __syncthreads();

    // ---- gi1: streamed Wi1, two k-half accumulators (bit-identical split) ----
    {
      u64 acc0s = pk2(bi1_r, 0.f), acc0g = acc0s;
      u64 acc1s = 0ull, acc1g = 0ull;
      const ulonglong2* hs_ = (const ulonglong2*)(sm + SOF_H0S + (1 - p) * 128);
      const ulonglong2* hg_ = (const ulonglong2*)(sm + SOF_H0G + (1 - p) * 128);
#pragma unroll 16
      for (int kk = 0; kk < 16; kk++) {
        ulonglong2 wi = *(const ulonglong2*)&wpk1F[kk * 384 + tid];
        ulonglong2 a2 = hs_[kk], g2 = hg_[kk];
        fma2(acc0s, wi.x, a2.x); fma2(acc0g, wi.x, g2.x);
        fma2(acc0s, wi.y, a2.y); fma2(acc0g, wi.y, g2.y);
      }
#pragma unroll 16
      for (int kk = 16; kk < 32; kk++) {
        ulonglong2 wi = *(const ulonglong2*)&wpk1F[kk * 384 + tid];
        ulonglong2 a2 = hs_[kk], g2 = hg_[kk];
        fma2(acc1s, wi.x, a2.x); fma2(acc1g, wi.x, g2.x);
        fma2(acc1s, wi.y, a2.y); fma2(acc1g, wi.y, g2.y);
      }
      gip[tid]       = make_float2(lsum(acc0s), lsum(acc0g));
      gip[384 + tid] = make_float2(lsum(acc1s), lsum(acc1g));
    }
    __syncthreads();

    // ---- gates#2 (tid<256) ----
    if (tid < 256) {
      int s = tid >> 7, j = tid & 127;
      float ir, iz, in_, hr, hz, hn, hp;
      if (s == 0) {
        ir = gip[j].x + gip[384 + j].x;
        iz = gip[j + 128].x + gip[384 + j + 128].x;
        in_ = gip[j + 256].x + gip[384 + j + 256].x;
        hr = gh1c[j].x; hz = gh1c[j + 128].x; hn = gh1c[j + 256].x;
        hp = sm[SOF_H1S + p * 128 + j];
      } else {
        ir = gip[j].y + gip[384 + j].y;
        iz = gip[j + 128].y + gip[384 + j + 128].y;
        in_ = gip[j + 256].y + gip[384 + j + 256].y;
        hr = gh1c[j].y; hz = gh1c[j + 128].y; hn = gh1c[j + 256].y;
        hp = sm[SOF_H1G + p * 128 + j];
      }
      float r0 = sigm(ir + hr), z0 = sigm(iz + hz), n0 = tanhf(in_ + r0 * hn);
      float hv = (1.f - z0) * n0 + z0 * hp;
      sm[(s ? SOF_H1G : SOF_H1S) + (1 - p) * 128 + j] = hv;
    }
    __syncthreads();

    // ---- logits (tid<100: both streams, two k-half partials summed) ----
    if (tid < 100) {
      const ulonglong2* hs_ = (const ulonglong2*)(sm + SOF_H1S + (1 - p) * 128);
      const ulonglong2* hg_ = (const ulonglong2*)(sm + SOF_H1G + (1 - p) * 128);
      u64 s0 = 0ull, s1 = 0ull, g0 = 0ull, g1 = 0ull;
#pragma unroll 16
      for (int kk = 0; kk < 16; kk++) {
        ulonglong2 y2 = Yr[kk];
        ulonglong2 a2 = hs_[kk], c2 = hg_[kk];
        fma2(s0, y2.x, a2.x); fma2(g0, y2.x, c2.x);
        fma2(s0, y2.y, a2.y); fma2(g0, y2.y, c2.y);
      }
#pragma unroll 16
      for (int kk = 0; kk < 16; kk++) {
        ulonglong2 y2 = Yr2[kk];
        ulonglong2 a2 = hs_[16 + kk], c2 = hg_[16 + kk];
        fma2(s1, y2.x, a2.x); fma2(g1, y2.x, c2.x);
        fma2(s1, y2.y, a2.y); fma2(g1, y2.y, c2.y);
      }
      ls[tid] = lsum(s0) + lsum(s1);
      lg[tid] = lsum(g0) + lsum(g1);
    }
    __syncthreads();

    // ---- reductions ----
    if (wrp == 0) {
      float bv = -3.4e38f; int bi_ = 0;
#pragma unroll
      for (int r = 0; r < 4; r++) {
        int i = lane + 32 * r;
        if (i < 100) {
          float v = ls[i] + gums[i];
          if (v > bv) { bv = v; bi_ = i; }
        }
      }
#pragma unroll
      for (int o = 16; o > 0; o >>= 1) {
        float ov = __shfl_xor_sync(0xffffffffu, bv, o);
        int   oi = __shfl_xor_sync(0xffffffffu, bi_, o);
        if (ov > bv || (ov == bv && oi < bi_)) { bv = ov; bi_ = oi; }
      }
      if (lane == 0) shi[0] = bi_;
    } else if (wrp == 1) {
      float bv = -3.4e38f; int bi_ = 0;
#pragma unroll
      for (int r = 0; r < 4; r++) {
        int i = lane + 32 * r;
        if (i < 100) {
          float v = lg[i];
          if (v > bv) { bv = v; bi_ = i; }
        }
      }
#pragma unroll
      for (int o = 16; o > 0; o >>= 1) {
        float ov = __shfl_xor_sync(0xffffffffu, bv, o);
        int   oi = __shfl_xor_sync(0xffffffffu, bi_, o);
        if (ov > bv || (ov == bv && oi < bi_)) { bv = ov; bi_ = oi; }
      }
      if (lane == 0) shi[1] = bi_;
    } else if (wrp == 2) {
      float s = 0.f;
#pragma unroll
      for (int r = 0; r < 4; r++) {
        int i = lane + 32 * r;
        if (i < 100) s += expf(ls[i]);
      }
#pragma unroll
      for (int o = 16; o > 0; o >>= 1) s += __shfl_xor_sync(0xffffffffu, s, o);
      if (lane == 0) red[1] = s;
    }
    __syncthreads();
    cur_s = shi[0];
    cur_g = shi[1];
    if (tid == 0) {
      solS[t + 1] = cur_s;
      solG[t + 1] = cur_g;
      out[OFF_LOGP + b * 99 + t] = ls[cur_s] - logf(red[1]);
    }
    __syncthreads();
  }

  // epilogue: distances + greedy solution matrix writes (gset folded in)
  if (tid < 99) {
    atomicAdd(&red[2], dis[b * 10000 + solS[tid] * 100 + solS[tid + 1]]);
    int u = solG[tid], v = solG[tid + 1];
    atomicAdd(&red[3], dis[b * 10000 + u * 100 + v]);
    out[OFF_GSOL + b * 10000 + u * 100 + v] = 1.0f;
  }
  __syncthreads();
  if (tid == 0) { out[OFF_SD + b] = red[2]; out[OFF_GD + b] = red[3]; }
}

extern "C" void kernel_launch(void* const* d_in, const int* in_sizes, int n_in,
                              void* d_out, int out_size) {
  const float* node   = (const float*)d_in[0];
  const float* demand = (const float*)d_in[1];
  const float* dis    = (const float*)d_in[2];
  const float* Wn0    = (const float*)d_in[3];
  const float* bn0    = (const float*)d_in[4];
  const float* Ws     = (const float*)d_in[5];
  const float* Wngh   = (const float*)d_in[6];
  const float* We     = (const float*)d_in[7];
  const float* be     = (const float*)d_in[8];
  const float* Wih    = (const float*)d_in[9];
  const float* Whh    = (const float*)d_in[10];
  const float* bih    = (const float*)d_in[11];
  const float* bhh    = (const float*)d_in[12];
  const float* Wq     = (const float*)d_in[13];
  const float* Wc     = (const float*)d_in[14];
  const float* bc     = (const float*)d_in[15];
  float* out = (float*)d_out;

  cudaFuncSetAttribute(k_aggr,   cudaFuncAttributeMaxDynamicSharedMemorySize, AGGR2_SMEM);
  cudaFuncSetAttribute(k_prep,   cudaFuncAttributeMaxDynamicSharedMemorySize, PREP_SMEM);
  cudaFuncSetAttribute(k_decode, cudaFuncAttributeMaxDynamicSharedMemorySize, DEC7_FLOATS * 4);

  k_front<<<4938, 256>>>(node, demand, Wn0, bn0, dis, We, be, Wc, bc, out);  // 0
  k_gemm2<<<400, 256>>>(0, Ws, Wngh);                                        // 1
  k_aggr<<<dim3(64, 4), 512, AGGR2_SMEM>>>(1);                               // 2
  k_gemm2<<<400, 256>>>(1, Ws + 16384, Wngh + 16384);                        // 3
  k_aggr<<<dim3(64, 4), 512, AGGR2_SMEM>>>(0);                               // 4
  k_gemm2<<<400, 256>>>(0, Ws + 32768, Wngh + 32768);                        // 5
  k_aggr<<<dim3(64, 4), 512, AGGR2_SMEM>>>(1);                               // 6
  // final h in g_buf1
  k_prep<<<2083, 384, PREP_SMEM>>>(Wih, bih, Wq, Whh);                       // 7
  k_decode<<<64, 384, DEC7_FLOATS * 4>>>(dis, bih, bhh, out);                // 8
}

// round 17
// speedup vs baseline: 1.7475x; 1.7475x over previous
#include <cuda_runtime.h>
#include <stdint.h>

#define OFF_LOGP 0
#define OFF_SD   6336
#define OFF_GD   6400
#define OFF_PRED 6464
#define OFF_GSOL 1286464

typedef unsigned long long u64;

__device__ float g_buf0[819200];
__device__ float g_buf1[819200];
__device__ float g_hWs[819200];
__device__ float g_hN[819200];
__device__ float g_A[640000];
__device__ float g_gum[633600];    // 99 * 6400
__device__ int   g_solg[6400];
__device__ float g_gi0[2457600];   // [64][100][384] x@Wih0+bih0
__device__ float g_y[819200];      // [64][100][128] (x@Wq^T)*scale
__device__ float4 g_wpk0[12288];   // Wh0 halves: [q][kk][192]
__device__ float4 g_wpk12[24576];  // [q][m][kk][192], m=0:Wi1 m=1:Wh1

// ---------------- threefry2x32 (exact JAX) ----------------
__device__ __forceinline__ void tf2x32(uint32_t k0, uint32_t k1,
                                       uint32_t c0, uint32_t c1,
                                       uint32_t& o0, uint32_t& o1) {
  uint32_t ks0 = k0, ks1 = k1, ks2 = k0 ^ k1 ^ 0x1BD11BDAu;
  uint32_t x0 = c0 + ks0, x1 = c1 + ks1;
#define TF_RND(R) { x0 += x1; x1 = __funnelshift_l(x1, x1, (R)); x1 ^= x0; }
  TF_RND(13) TF_RND(15) TF_RND(26) TF_RND(6)   x0 += ks1; x1 += ks2 + 1u;
  TF_RND(17) TF_RND(29) TF_RND(16) TF_RND(24)  x0 += ks2; x1 += ks0 + 2u;
  TF_RND(13) TF_RND(15) TF_RND(26) TF_RND(6)   x0 += ks0; x1 += ks1 + 3u;
  TF_RND(17) TF_RND(29) TF_RND(16) TF_RND(24)  x0 += ks1; x1 += ks2 + 4u;
  TF_RND(13) TF_RND(15) TF_RND(26) TF_RND(6)   x0 += ks2; x1 += ks0 + 5u;
#undef TF_RND
  o0 = x0; o1 = x1;
}

// ---------------- f32x2 helpers ----------------
__device__ __forceinline__ u64 pk2(float lo, float hi) {
  u64 d; asm("mov.b64 %0, {%1, %2};" : "=l"(d) : "f"(lo), "f"(hi)); return d;
}
__device__ __forceinline__ void upk2(float& lo, float& hi, u64 d) {
  asm("mov.b64 {%0, %1}, %2;" : "=f"(lo), "=f"(hi) : "l"(d));
}
__device__ __forceinline__ void fma2(u64& acc, u64 a, u64 b) {
  asm("fma.rn.f32x2 %0, %1, %2, %3;" : "=l"(acc) : "l"(a), "l"(b), "l"(acc));
}
__device__ __forceinline__ float lsum(u64 d) {
  float lo, hi; upk2(lo, hi, d); return lo + hi;
}

// ---------------- cluster / DSMEM helpers ----------------
__device__ __forceinline__ uint32_t smem_u32(const void* p) {
  uint32_t a;
  asm("{ .reg .u64 t; cvta.to.shared.u64 t, %1; cvt.u32.u64 %0, t; }" : "=r"(a) : "l"(p));
  return a;
}
__device__ __forceinline__ uint32_t ctarank() {
  uint32_t r; asm("mov.u32 %0, %%cluster_ctarank;" : "=r"(r)); return r;
}
__device__ __forceinline__ void peer_st_f1(uint32_t laddr, uint32_t peer, float x) {
  uint32_t ra;
  asm("mapa.shared::cluster.u32 %0, %1, %2;" : "=r"(ra) : "r"(laddr), "r"(peer));
  asm volatile("st.shared::cluster.b32 [%0], %1;"
               :: "r"(ra), "r"(__float_as_uint(x)) : "memory");
}
#define CSYNC() do { \
  asm volatile("barrier.cluster.arrive.aligned;" ::: "memory"); \
  asm volatile("barrier.cluster.wait.aligned;"  ::: "memory"); } while (0)

// ---------------- mega front: h0 | softA | pred | gzero | pack2 | gumbel ----------------
__global__ void k_front(const float* __restrict__ node, const float* __restrict__ demand,
                        const float* __restrict__ Wn0, const float* __restrict__ bn0,
                        const float* __restrict__ dis,
                        const float* __restrict__ We, const float* __restrict__ be,
                        const float* __restrict__ Wc, const float* __restrict__ bc,
                        const float* __restrict__ Wih, const float* __restrict__ Whh,
                        float* __restrict__ out) {
  const int bx = blockIdx.x, tid = threadIdx.x;
  if (bx < 3200) {
    // ---- h0 ----
    int idx = bx * 256 + tid;
    int row = idx >> 7, j = idx & 127;
    float v = bn0[j];
    v = fmaf(node[row * 2],     Wn0[j],       v);
    v = fmaf(node[row * 2 + 1], Wn0[128 + j], v);
    v = fmaf(demand[row],       Wn0[256 + j], v);
    g_buf0[idx] = fmaxf(v, 0.f);
  } else if (bx < 4000) {
    // ---- softA ----
    int row  = (bx - 3200) * 8 + (tid >> 5);
    int lane = tid & 31;
    const float* d = dis + row * 100;
    float v0 = -d[lane], v1 = -d[lane + 32], v2 = -d[lane + 64];
    float v3 = (lane + 96 < 100) ? -d[lane + 96] : -3.4e38f;
    float m = fmaxf(fmaxf(v0, v1), fmaxf(v2, v3));
#pragma unroll
    for (int o = 16; o > 0; o >>= 1) m = fmaxf(m, __shfl_xor_sync(0xffffffffu, m, o));
    float e0 = expf(v0 - m), e1 = expf(v1 - m), e2 = expf(v2 - m);
    float e3 = (lane + 96 < 100) ? expf(v3 - m) : 0.f;
    float s = e0 + e1 + e2 + e3;
#pragma unroll
    for (int o = 16; o > 0; o >>= 1) s += __shfl_xor_sync(0xffffffffu, s, o);
    float* Ar = g_A + row * 100;
    Ar[lane] = e0 / s; Ar[lane + 32] = e1 / s; Ar[lane + 64] = e2 / s;
    if (lane + 96 < 100) Ar[lane + 96] = e3 / s;
  } else if (bx < 4313) {
    // ---- predict_matrix ----
    __shared__ float wsm[4][128];
    for (int i = tid; i < 128; i += 256) {
      wsm[0][i] = We[i]; wsm[1][i] = be[i];
      wsm[2][i] = Wc[2 * i]; wsm[3][i] = Wc[2 * i + 1];
    }
    __syncthreads();
    int t0 = ((bx - 4000) * 256 + tid) * 8;
    if (t0 >= 640000) return;
    float d[8], y0[8], y1[8];
#pragma unroll
    for (int u = 0; u < 8; u++) {
      int pp = t0 + u;
      d[u] = (pp < 640000) ? __ldg(dis + pp) : 0.f;
      y0[u] = 0.f; y1[u] = 0.f;
    }
#pragma unroll 4
    for (int k = 0; k < 128; k++) {
      float we = wsm[0][k], bee = wsm[1][k];
      float w0 = wsm[2][k], w1 = wsm[3][k];
#pragma unroll
      for (int u = 0; u < 8; u++) {
        float e = fmaxf(fmaf(d[u], we, bee), 0.f);
        y0[u] = fmaf(e, w0, y0[u]);
        y1[u] = fmaf(e, w1, y1[u]);
      }
    }
    float bc0 = __ldg(bc), bc1 = __ldg(bc + 1);
#pragma unroll
    for (int u = 0; u < 8; u++) {
      int pp = t0 + u;
      if (pp < 640000) {
        float a = y0[u] + bc0, bb = y1[u] + bc1;
        float m = fmaxf(a, bb);
        float e0 = expf(a - m), e1 = expf(bb - m), s = e0 + e1;
        *(float2*)&out[OFF_PRED + pp * 2] = make_float2(e0 / s, e1 / s);
      }
    }
  } else if (bx < 4938) {
    // ---- gzero ----
    int idx = (bx - 4313) * 256 + tid;
    *(float4*)&out[OFF_GSOL + idx * 4] = make_float4(0.f, 0.f, 0.f, 0.f);
  } else if (bx < 5514) {
    // ---- pack2 (576 blocks * 256 = 147456) ----
    int idx = (bx - 4938) * 256 + tid;
    if (idx < 49152) {
      int f4 = idx >> 2, u = idx & 3;
      int q = f4 / 6144, r4 = f4 % 6144;
      int kk = r4 / 192, o = r4 % 192;
      int colq = (o >> 6) * 128 + (q << 6) + (o & 63);
      ((float*)g_wpk0)[idx] = Whh[(4 * kk + u) * 384 + colq];
    } else {
      int i2 = idx - 49152;
      int f4 = i2 >> 2, u = i2 & 3;
      int unit = f4 / 6144, r4 = f4 % 6144;
      int q = unit >> 1, m = unit & 1;
      int kk = r4 / 192, o = r4 % 192;
      int colq = (o >> 6) * 128 + (q << 6) + (o & 63);
      const float* srcp = m ? (Whh + 49152) : (Wih + 49152);
      ((float*)g_wpk12)[i2] = srcp[(4 * kk + u) * 384 + colq];
    }
  } else {
    // ---- gumbel: t = bx - 5514 ----
    int t = bx - 5514;
    __shared__ uint32_t sk0, sk1;
    if (tid == 0) {
      uint32_t k0 = 0u, k1 = 42u, a, b;
      tf2x32(k0, k1, 0u, 0u, a, b); k0 = a; k1 = b;
      for (int i = 0; i < t; i++) { tf2x32(k0, k1, 0u, 0u, a, b); k0 = a; k1 = b; }
      tf2x32(k0, k1, 0u, 1u, a, b); sk0 = a; sk1 = b;
    }
    __syncthreads();
    const float TINY = 1.17549435e-38f;
    uint32_t s0 = sk0, s1 = sk1;
    for (int i = tid; i < 6400; i += 256) {
      uint32_t o0, o1;
      tf2x32(s0, s1, 0u, (uint32_t)i, o0, o1);
      uint32_t bits = o0 ^ o1;
      float f = __uint_as_float((bits >> 9) | 0x3f800000u) - 1.0f;
      float u = fmaxf(TINY, f + TINY);
      g_gum[t * 6400 + i] = -logf(-logf(u));
    }
  }
}

// ---------------- hWs/hN; 16 rows per block, 256 threads ----------------
__global__ void k_gemm2(int src, const float* __restrict__ W1, const float* __restrict__ W2) {
  const float* h = src ? g_buf1 : g_buf0;
  __shared__ float acts[16][128];
  int tid = threadIdx.x;
  int j = tid & 127, half = tid >> 7;
  int row0 = blockIdx.x * 16;
  for (int i = tid; i < 2048; i += 256) acts[i >> 7][i & 127] = h[row0 * 128 + i];
  __syncthreads();
  float aS[8], aN[8];
#pragma unroll
  for (int r = 0; r < 8; r++) { aS[r] = 0.f; aN[r] = 0.f; }
#pragma unroll 8
  for (int k = 0; k < 128; k++) {
    float ws = __ldg(W1 + k * 128 + j);
    float wn = __ldg(W2 + k * 128 + j);
#pragma unroll
    for (int r = 0; r < 8; r++) {
      float a = acts[half * 8 + r][k];
      aS[r] = fmaf(a, ws, aS[r]);
      aN[r] = fmaf(a, wn, aN[r]);
    }
  }
#pragma unroll
  for (int r = 0; r < 8; r++) {
    g_hWs[(row0 + half * 8 + r) * 128 + j] = aS[r];
    g_hN [(row0 + half * 8 + r) * 128 + j] = aN[r];
  }
}

// ---------------- h_next = relu(hWs + A @ hN); grid (64,4), 512 threads ----------------
#define AGGR2_SMEM ((12800 + 2500) * 4)
__global__ void k_aggr(int dst) {
  extern __shared__ float sm[];
  float* hN_s = sm;
  float* A_s  = sm + 12800;
  int b = blockIdx.x, r0 = blockIdx.y * 25, tid = threadIdx.x;
  for (int i = tid; i < 12800; i += 512) hN_s[i] = g_hN[b * 12800 + i];
  for (int i = tid; i < 2500; i += 512)  A_s[i]  = g_A [b * 10000 + r0 * 100 + i];
  __syncthreads();
  float* ho = dst ? g_buf1 : g_buf0;
  int j = tid & 127, g = tid >> 7;
  for (int il = g; il < 25; il += 8) {
    int i2 = il + 4;
    bool two = i2 < 25;
    float a0 = 0.f, a1 = 0.f, c0 = 0.f, c1 = 0.f;
#pragma unroll 10
    for (int p = 0; p < 100; p += 2) {
      float h0v = hN_s[p * 128 + j], h1v = hN_s[(p + 1) * 128 + j];
      a0 = fmaf(A_s[il * 100 + p],     h0v, a0);
      a1 = fmaf(A_s[il * 100 + p + 1], h1v, a1);
      if (two) {
        c0 = fmaf(A_s[i2 * 100 + p],     h0v, c0);
        c1 = fmaf(A_s[i2 * 100 + p + 1], h1v, c1);
      }
    }
    int row = b * 100 + r0 + il;
    ho[row * 128 + j] = fmaxf(g_hWs[row * 128 + j] + a0 + a1, 0.f);
    if (two)
      ho[(row + 4) * 128 + j] = fmaxf(g_hWs[(row + 4) * 128 + j] + c0 + c1, 0.f);
  }
}

// ---------------- prep (gi0 | y) — only the parts needing final h ----------------
#define PREP_SMEM (17536 * 4)
__global__ void k_prep(const float* __restrict__ Wih, const float* __restrict__ bih,
                       const float* __restrict__ Wq) {
  extern __shared__ float smd[];
  const int bx = blockIdx.x, tid = threadIdx.x;
  if (bx < 800) {
    float* acts = smd;   // [8][128]
    int o = tid;
    int row0 = bx * 8;
    for (int i = o; i < 1024; i += 384) acts[i] = g_buf1[row0 * 128 + i];
    __syncthreads();
    float a[8];
    float bv = bih[o];
#pragma unroll
    for (int r = 0; r < 8; r++) a[r] = bv;
#pragma unroll 8
    for (int k = 0; k < 128; k++) {
      float w = __ldg(Wih + k * 384 + o);
#pragma unroll
      for (int r = 0; r < 8; r++) a[r] = fmaf(acts[r * 128 + k], w, a[r]);
    }
#pragma unroll
    for (int r = 0; r < 8; r++) g_gi0[(row0 + r) * 384 + o] = a[r];
  } else {
    float* wq_t = smd;            // [j][k] padded 129
    float* acts = smd + 16512;    // [8][128]
    int row0 = (bx - 800) * 8;
    for (int i = tid; i < 16384; i += 384) {
      int k = i >> 7, j = i & 127;
      wq_t[j * 129 + k] = Wq[i];
    }
    for (int i = tid; i < 1024; i += 384) acts[i] = g_buf1[row0 * 128 + i];
    __syncthreads();
    if (tid < 128) {
      const float scale = (float)(1.0 / (double)sqrtf(128.0f));
      int k = tid;
      float a[8];
#pragma unroll
      for (int r = 0; r < 8; r++) a[r] = 0.f;
#pragma unroll 4
      for (int jj = 0; jj < 128; jj++) {
        float w = wq_t[jj * 129 + k];
#pragma unroll
        for (int r = 0; r < 8; r++) a[r] = fmaf(acts[r * 128 + jj], w, a[r]);
      }
#pragma unroll
      for (int r = 0; r < 8; r++) g_y[(row0 + r) * 128 + k] = a[r] * scale;
    }
  }
}

__device__ __forceinline__ float sigm(float x) { return 1.f / (1.f + expf(-x)); }

// ---------------- cluster-of-2 decoder v6 (R14, best known) ----------------
#define SOF_WH0   0        // float4[6144]
#define SOF_WP1R  24576    // float4[5376]
#define SOF_YC    46080    // [100][68]
#define SOF_H0SA  52880    // [2][128]
#define SOF_H0GA  53136
#define SOF_H1SA  53392
#define SOF_H1GA  53648
#define SOF_GI2   53904    // float2[192]
#define SOF_GH2   54288
#define SOF_GH1C  54672
#define SOF_GIP   55056    // float2[2][192]
#define SOF_PLS   55824    // [200]
#define SOF_PLG   56024    // [200]
#define SOF_GUM   56224    // [100]
#define SOF_SHI   56324
#define SOF_RED   56328
#define SOF_SOLS  56332
#define SOF_SOLG  56432
#define DEC6_FLOATS 56536
__global__ void __cluster_dims__(2, 1, 1) __launch_bounds__(384, 1) k_decode(
    const float* __restrict__ dis, const float* __restrict__ bih,
    const float* __restrict__ bhh, float* __restrict__ out) {
  extern __shared__ float sm[];
  const int tid = threadIdx.x;
  const int b = blockIdx.x >> 1;
  const uint32_t rank = ctarank();
  const uint32_t peer = rank ^ 1u;
  const int lane = tid & 31, wrp = tid >> 5;
  const bool isA = tid < 192;
  const int c = isA ? tid : tid - 192;
  const int col = ((c >> 6) << 7) + ((int)rank << 6) + (c & 63);

  float*  wh0s = sm + SOF_WH0;
  float*  wp1r = sm + SOF_WP1R;
  float*  yc   = sm + SOF_YC;
  float2* gi2  = (float2*)(sm + SOF_GI2);
  float2* gh2  = (float2*)(sm + SOF_GH2);
  float2* gh1c = (float2*)(sm + SOF_GH1C);
  float2* gip  = (float2*)(sm + SOF_GIP);
  float*  gums = sm + SOF_GUM;
  int*    shi  = (int*)(sm + SOF_SHI);
  float*  red  = sm + SOF_RED;
  int*    solS = (int*)(sm + SOF_SOLS);
  int*    solG = (int*)(sm + SOF_SOLG);

  const uint32_t sbase = smem_u32(sm);
  const float* wp1g = (const float*)(g_wpk12 + ((int)rank * 2) * 6144);
  const float* wp2g = (const float*)(g_wpk12 + ((int)rank * 2 + 1) * 6144);

  // prologue
  {
    const float4* w0src = g_wpk0 + rank * 6144;
    float4* wh0s4 = (float4*)wh0s;
    float4* wp1r4 = (float4*)wp1r;
    for (int i = tid; i < 6144; i += 384) wh0s4[i] = w0src[i];
    for (int i = tid; i < 5376; i += 384) wp1r4[i] = ((const float4*)wp1g)[i];
    for (int i = tid; i < 6400; i += 384) {
      int row = i >> 6, kk = i & 63;
      yc[row * 68 + kk] = g_y[b * 12800 + row * 128 + (int)rank * 64 + kk];
    }
    for (int i = tid; i < 256; i += 384) {
      sm[SOF_H0SA + i] = 0.f; sm[SOF_H0GA + i] = 0.f;
      sm[SOF_H1SA + i] = 0.f; sm[SOF_H1GA + i] = 0.f;
    }
    if (tid == 0) { solS[0] = 0; solG[0] = 0; red[2] = 0.f; red[3] = 0.f; }
  }
  float bh0_r = 0.f, bi1_r = 0.f, bh1_r = 0.f;
  if (isA) { bh0_r = bhh[col]; bi1_r = bih[384 + col]; }
  else     { bh1_r = bhh[384 + col]; }
  int cur_s = 0, cur_g = 0;
  __syncthreads();
  CSYNC();

  for (int t = 0; t < 99; t++) {
    const int p = t & 1;
    // ---- ph1: early loads ----
    if (tid < 100) gums[tid] = __ldg(&g_gum[t * 6400 + b * 100 + tid]);
    float gi_s = 0.f, gi_g = 0.f;
    ulonglong2 wst[4];
    if (isA) {
      gi_s = __ldg(&g_gi0[(b * 100 + cur_s) * 384 + col]);
      gi_g = __ldg(&g_gi0[(b * 100 + cur_g) * 384 + col]);
    } else {
#pragma unroll
      for (int u = 0; u < 4; u++)
        wst[u] = *(const ulonglong2*)&wp1g[((28 + u) * 192 + c) * 4];
    }

    // ---- ph2: parallel gemvs, f32x2 ----
    if (isA) {
      u64 accs = pk2(bh0_r, 0.f), accg = pk2(bh0_r, 0.f);
      const ulonglong2* hs = (const ulonglong2*)(sm + SOF_H0SA + p * 128);
      const ulonglong2* hg = (const ulonglong2*)(sm + SOF_H0GA + p * 128);
#pragma unroll 16
      for (int kk = 0; kk < 32; kk++) {
        ulonglong2 w = *(const ulonglong2*)&wh0s[(kk * 192 + c) * 4];
        ulonglong2 a2 = hs[kk], g2 = hg[kk];
        fma2(accs, w.x, a2.x); fma2(accg, w.x, g2.x);
        fma2(accs, w.y, a2.y); fma2(accg, w.y, g2.y);
      }
      gh2[c] = make_float2(lsum(accs), lsum(accg));
      gi2[c] = make_float2(gi_s, gi_g);
    } else {
      u64 accs = pk2(bh1_r, 0.f), accg = pk2(bh1_r, 0.f);
      const ulonglong2* hs = (const ulonglong2*)(sm + SOF_H1SA + p * 128);
      const ulonglong2* hg = (const ulonglong2*)(sm + SOF_H1GA + p * 128);
#pragma unroll 16
      for (int kk = 0; kk < 32; kk++) {
        ulonglong2 w = *(const ulonglong2*)&wp2g[(kk * 192 + c) * 4];
        ulonglong2 a2 = hs[kk], g2 = hg[kk];
        fma2(accs, w.x, a2.x); fma2(accg, w.x, g2.x);
        fma2(accs, w.y, a2.y); fma2(accg, w.y, g2.y);
      }
      gh1c[c] = make_float2(lsum(accs), lsum(accg));
    }
    __syncthreads();

    // ---- gates#1 (tid<128, one stream per thread) ----
    if (tid < 128) {
      int s = tid >> 6, jj = tid & 63;
      int j = ((int)rank << 6) + jj;
      float ir, iz, in_, hr, hz, hn, hp;
      if (s == 0) {
        ir = gi2[jj].x; iz = gi2[jj + 64].x; in_ = gi2[jj + 128].x;
        hr = gh2[jj].x; hz = gh2[jj + 64].x; hn  = gh2[jj + 128].x;
        hp = sm[SOF_H0SA + p * 128 + j];
      } else {
        ir = gi2[jj].y; iz = gi2[jj + 64].y; in_ = gi2[jj + 128].y;
        hr = gh2[jj].y; hz = gh2[jj + 64].y; hn  = gh2[jj + 128].y;
        hp = sm[SOF_H0GA + p * 128 + j];
      }
      float r0 = sigm(ir + hr), z0 = sigm(iz + hz), n0 = tanhf(in_ + r0 * hn);
      float hv = (1.f - z0) * n0 + z0 * hp;
      int base = (s ? SOF_H0GA : SOF_H0SA) + (1 - p) * 128 + j;
      sm[base] = hv;
      peer_st_f1(sbase + ((uint32_t)base << 2), peer, hv);
    }
    CSYNC();   // S1: full h0_new everywhere

    // ---- ph5: gi1 gemv, k-split across 384 threads, f32x2 ----
    {
      const int kh = isA ? 0 : 1;
      u64 accs = isA ? pk2(bi1_r, 0.f) : 0ull;
      u64 accg = accs;
      const ulonglong2* hs = (const ulonglong2*)(sm + SOF_H0SA + (1 - p) * 128);
      const ulonglong2* hg = (const ulonglong2*)(sm + SOF_H0GA + (1 - p) * 128);
#pragma unroll 16
      for (int u = 0; u < 16; u++) {
        int kk = kh * 16 + u;
        ulonglong2 wi;
        if (kk < 28) wi = *(const ulonglong2*)&wp1r[(kk * 192 + c) * 4];
        else wi = wst[kk - 28];
        ulonglong2 a2 = hs[kk], g2 = hg[kk];
        fma2(accs, wi.x, a2.x); fma2(accg, wi.x, g2.x);
        fma2(accs, wi.y, a2.y); fma2(accg, wi.y, g2.y);
      }
      gip[kh * 192 + c] = make_float2(lsum(accs), lsum(accg));
    }
    __syncthreads();

    // ---- gates#2 (tid<128, one stream per thread) ----
    if (tid < 128) {
      int s = tid >> 6, jj = tid & 63;
      int j = ((int)rank << 6) + jj;
      float ir, iz, in_, hr, hz, hn, hp;
      if (s == 0) {
        ir = gip[jj].x + gip[192 + jj].x;
        iz = gip[jj + 64].x + gip[256 + jj].x;
        in_ = gip[jj + 128].x + gip[320 + jj].x;
        hr = gh1c[jj].x; hz = gh1c[jj + 64].x; hn = gh1c[jj + 128].x;
        hp = sm[SOF_H1SA + p * 128 + j];
      } else {
        ir = gip[jj].y + gip[192 + jj].y;
        iz = gip[jj + 64].y + gip[256 + jj].y;
        in_ = gip[jj + 128].y + gip[320 + jj].y;
        hr = gh1c[jj].y; hz = gh1c[jj + 64].y; hn = gh1c[jj + 128].y;
        hp = sm[SOF_H1GA + p * 128 + j];
      }
      float r0 = sigm(ir + hr), z0 = sigm(iz + hz), n0 = tanhf(in_ + r0 * hn);
      float hv = (1.f - z0) * n0 + z0 * hp;
      int base = (s ? SOF_H1GA : SOF_H1SA) + (1 - p) * 128 + j;
      sm[base] = hv;
      peer_st_f1(sbase + ((uint32_t)base << 2), peer, hv);
    }
    __syncthreads();   // local h1 half visible for logit partials

    // ---- ph7: logit partials, 200 threads ----
    if (tid < 200) {
      int s = (tid >= 100) ? 1 : 0;
      int row = s ? tid - 100 : tid;
      const ulonglong2* h = (const ulonglong2*)(sm + (s ? SOF_H1GA : SOF_H1SA) +
                                                (1 - p) * 128 + (int)rank * 64);
      const float* yr = yc + row * 68;
      u64 acc = 0ull;
#pragma unroll 16
      for (int kk = 0; kk < 16; kk++) {
        ulonglong2 y2 = *(const ulonglong2*)&yr[4 * kk];
        ulonglong2 a2 = h[kk];
        fma2(acc, y2.x, a2.x);
        fma2(acc, y2.y, a2.y);
      }
      float v = lsum(acc);
      int po = (s ? SOF_PLG : SOF_PLS) + (int)rank * 100 + row;
      sm[po] = v;
      peer_st_f1(sbase + ((uint32_t)po << 2), peer, v);
    }
    CSYNC();   // S2: h1_new + logit partials everywhere

    // ---- reductions directly on partials ----
    if (wrp == 0) {
      float bv = -3.4e38f; int bi_ = 0;
#pragma unroll
      for (int r = 0; r < 4; r++) {
        int i = lane + 32 * r;
        if (i < 100) {
          float v = (sm[SOF_PLS + i] + sm[SOF_PLS + 100 + i]) + gums[i];
          if (v > bv) { bv = v; bi_ = i; }
        }
      }
#pragma unroll
      for (int o = 16; o > 0; o >>= 1) {
        float ov = __shfl_xor_sync(0xffffffffu, bv, o);
        int   oi = __shfl_xor_sync(0xffffffffu, bi_, o);
        if (ov > bv || (ov == bv && oi < bi_)) { bv = ov; bi_ = oi; }
      }
      if (lane == 0) shi[0] = bi_;
    } else if (wrp == 1) {
      float bv = -3.4e38f; int bi_ = 0;
#pragma unroll
      for (int r = 0; r < 4; r++) {
        int i = lane + 32 * r;
        if (i < 100) {
          float v = sm[SOF_PLG + i] + sm[SOF_PLG + 100 + i];
          if (v > bv) { bv = v; bi_ = i; }
        }
      }
#pragma unroll
      for (int o = 16; o > 0; o >>= 1) {
        float ov = __shfl_xor_sync(0xffffffffu, bv, o);
        int   oi = __shfl_xor_sync(0xffffffffu, bi_, o);
        if (ov > bv || (ov == bv && oi < bi_)) { bv = ov; bi_ = oi; }
      }
      if (lane == 0) shi[1] = bi_;
    } else if (wrp == 2) {
      float s = 0.f;
#pragma unroll
      for (int r = 0; r < 4; r++) {
        int i = lane + 32 * r;
        if (i < 100) s += expf(sm[SOF_PLS + i] + sm[SOF_PLS + 100 + i]);
      }
#pragma unroll
      for (int o = 16; o > 0; o >>= 1) s += __shfl_xor_sync(0xffffffffu, s, o);
      if (lane == 0) red[1] = s;
    }
    __syncthreads();
    cur_s = shi[0];
    cur_g = shi[1];
    if (tid == 0) {
      solS[t + 1] = cur_s;
      solG[t + 1] = cur_g;
      if (rank == 0)
        out[OFF_LOGP + b * 99 + t] =
            (sm[SOF_PLS + cur_s] + sm[SOF_PLS + 100 + cur_s]) - logf(red[1]);
    }
    // no trailing sync: next-iter writes separated by S1'/S2' cluster barriers
  }

  CSYNC();
  if (rank == 0) {
    if (tid < 99) {
      atomicAdd(&red[2], dis[b * 10000 + solS[tid] * 100 + solS[tid + 1]]);
      atomicAdd(&red[3], dis[b * 10000 + solG[tid] * 100 + solG[tid + 1]]);
    }
    for (int i = tid; i < 100; i += 384) g_solg[b * 100 + i] = solG[i];
    __syncthreads();
    if (tid == 0) { out[OFF_SD + b] = red[2]; out[OFF_GD + b] = red[3]; }
  }
}

__global__ void k_gset(float* __restrict__ out) {
  int b = blockIdx.x, t = threadIdx.x;
  if (t < 99) {
    int u = g_solg[b * 100 + t], v = g_solg[b * 100 + t + 1];
    out[OFF_GSOL + b * 10000 + u * 100 + v] = 1.0f;
  }
}

extern "C" void kernel_launch(void* const* d_in, const int* in_sizes, int n_in,
                              void* d_out, int out_size) {
  const float* node   = (const float*)d_in[0];
  const float* demand = (const float*)d_in[1];
  const float* dis    = (const float*)d_in[2];
  const float* Wn0    = (const float*)d_in[3];
  const float* bn0    = (const float*)d_in[4];
  const float* Ws     = (const float*)d_in[5];
  const float* Wngh   = (const float*)d_in[6];
  const float* We     = (const float*)d_in[7];
  const float* be     = (const float*)d_in[8];
  const float* Wih    = (const float*)d_in[9];
  const float* Whh    = (const float*)d_in[10];
  const float* bih    = (const float*)d_in[11];
  const float* bhh    = (const float*)d_in[12];
  const float* Wq     = (const float*)d_in[13];
  const float* Wc     = (const float*)d_in[14];
  const float* bc     = (const float*)d_in[15];
  float* out = (float*)d_out;

  cudaFuncSetAttribute(k_aggr,   cudaFuncAttributeMaxDynamicSharedMemorySize, AGGR2_SMEM);
  cudaFuncSetAttribute(k_prep,   cudaFuncAttributeMaxDynamicSharedMemorySize, PREP_SMEM);
  cudaFuncSetAttribute(k_decode, cudaFuncAttributeMaxDynamicSharedMemorySize, DEC6_FLOATS * 4);

  k_front<<<5613, 256>>>(node, demand, Wn0, bn0, dis, We, be, Wc, bc, Wih, Whh, out);  // 0
  k_gemm2<<<400, 256>>>(0, Ws, Wngh);                                        // 1
  k_aggr<<<dim3(64, 4), 512, AGGR2_SMEM>>>(1);                               // 2
  k_gemm2<<<400, 256>>>(1, Ws + 16384, Wngh + 16384);                        // 3
  k_aggr<<<dim3(64, 4), 512, AGGR2_SMEM>>>(0);                               // 4
  k_gemm2<<<400, 256>>>(0, Ws + 32768, Wngh + 32768);                        // 5
  k_aggr<<<dim3(64, 4), 512, AGGR2_SMEM>>>(1);                               // 6
  // final h in g_buf1
  k_prep<<<1600, 384, PREP_SMEM>>>(Wih, bih, Wq);                            // 7
  k_decode<<<128, 384, DEC6_FLOATS * 4>>>(dis, bih, bhh, out);               // 8
  k_gset<<<64, 128>>>(out);                                                  // 9
}